// round 9
// baseline (speedup 1.0000x reference)
#include <cuda_runtime.h>
#include <math.h>

#define B_    32
#define FBINS 128
#define TTOT  2400
#define HDIM  256
#define SEG_  24
#define SSEG  100
#define BS_   3200   // B_*SSEG

// ---------------- scratch (device globals) ----------------------------------
__device__ float g_xT[B_*TTOT*FBINS];      // (B, T, F) transposed input
__device__ float g_rec[B_*TTOT*FBINS];     // (B, T, F) reconstruction
__device__ float g_xw_oe[B_*TTOT*1024];    // hoisted oe input gates (76800, 1024)
__device__ float g_hA[BS_*HDIM];           // oe hidden ping
__device__ float g_hB[BS_*HDIM];           // oe hidden pong
__device__ float g_c[BS_*HDIM];            // oe cell -> c_seg
__device__ float g_xw_ie[BS_*1024];
__device__ float g_bot[B_*HDIM];           // bottleneck (final cell of ie)
__device__ float g_xw_id[B_*1024];
__device__ float g_dec[BS_*HDIM];          // inner-decoder hidden states (B,S,H)
__device__ float g_xw_od[BS_*512];
__device__ float g_h2A[BS_*FBINS];         // od hidden ping
__device__ float g_h2B[BS_*FBINS];         // od hidden pong
__device__ float g_c2[BS_*FBINS];          // od cell
// interleaved weights (col = 4*u + g, g in {i,f,g,o}) / fused biases
__device__ float g_oe_wT[(FBINS+HDIM)*1024];   // rows 0..127: WihT, 128..383: WhhT
__device__ float g_oe_b[1024];
__device__ float g_ie_wihT[HDIM*1024];
__device__ float g_ie_whhI[HDIM*1024];
__device__ float g_ie_b[1024];
__device__ float g_id_wihT[HDIM*1024];
__device__ float g_id_whhI[HDIM*1024];
__device__ float g_id_b[1024];
__device__ float g_od_wihT[HDIM*512];
__device__ float g_od_whhT[FBINS*512];
__device__ float g_od_b[512];

__device__ __forceinline__ float sigf(float x) { return 1.0f / (1.0f + __expf(-x)); }

// ---------------- batched tiled transpose: src (batch, R, C) -> dst (batch, C, R)
__global__ void btrans(float* __restrict__ dst, const float* __restrict__ src, int R, int C) {
    __shared__ float tile[32][33];
    int b  = blockIdx.z;
    int c0 = blockIdx.x * 32, r0 = blockIdx.y * 32;
    const float* s = src + (size_t)b * R * C;
    float*       d = dst + (size_t)b * R * C;
    int tx = threadIdx.x, ty = threadIdx.y;   // 32 x 8
    #pragma unroll
    for (int i = 0; i < 32; i += 8) {
        int r = r0 + ty + i, c = c0 + tx;
        if (r < R && c < C) tile[ty + i][tx] = s[r * C + c];
    }
    __syncthreads();
    #pragma unroll
    for (int i = 0; i < 32; i += 8) {
        int c = c0 + ty + i, r = r0 + tx;
        if (c < C && r < R) d[c * R + r] = tile[tx][ty + i];
    }
}

// ---- weight interleave: dst[k*(4U) + 4u+g] = src[(g*U+u)*K + k] -------------
__device__ __forceinline__ void pk(float* __restrict__ dst, const float* __restrict__ src,
                                   int U, int K, long i) {
    int n4 = 4 * U;
    int col = (int)(i % n4);
    long k  = i / n4;
    int u = col >> 2, g = col & 3;
    dst[i] = src[(long)(g * U + u) * K + k];
}

// ---- one mega pack kernel: all biases + all interleaved weights -------------
__global__ void pack_all(const float* oe_wih, const float* oe_whh,
                         const float* ie_wih, const float* ie_whh,
                         const float* id_wih, const float* id_whh,
                         const float* od_wih, const float* od_whh,
                         const float* oe_bih, const float* oe_bhh,
                         const float* ie_bih, const float* ie_bhh,
                         const float* id_bih, const float* id_bhh,
                         const float* od_bih, const float* od_bhh,
                         float* oe_wT, float* ie_wihT, float* ie_whhI,
                         float* id_wihT, float* id_whhI,
                         float* od_wihT, float* od_whhT,
                         float* oe_b, float* ie_b, float* id_b, float* od_b) {
    long idx = (long)blockIdx.x * blockDim.x + threadIdx.x;
    if (idx < 1024) {
        int u = (int)idx >> 2, g = (int)idx & 3;
        int s = g * 256 + u;
        oe_b[idx] = oe_bih[s] + oe_bhh[s];
        ie_b[idx] = ie_bih[s] + ie_bhh[s];
        id_b[idx] = id_bih[s] + id_bhh[s];
        return;
    }
    if (idx < 1536) {
        int i = (int)idx - 1024;
        int u = i >> 2, g = i & 3;
        int s = g * 128 + u;
        od_b[i] = od_bih[s] + od_bhh[s];
        return;
    }
    long w = idx - 1536;
    if (w < 131072)            { pk(oe_wT,            oe_wih, 256, 128, w); return; }
    if ((w -= 131072) < 262144){ pk(oe_wT + 131072,   oe_whh, 256, 256, w); return; }
    if ((w -= 262144) < 262144){ pk(ie_wihT,          ie_wih, 256, 256, w); return; }
    if ((w -= 262144) < 262144){ pk(ie_whhI,          ie_whh, 256, 256, w); return; }
    if ((w -= 262144) < 262144){ pk(id_wihT,          id_wih, 256, 256, w); return; }
    if ((w -= 262144) < 262144){ pk(id_whhI,          id_whh, 256, 256, w); return; }
    if ((w -= 262144) < 131072){ pk(od_wihT,          od_wih, 128, 256, w); return; }
    if ((w -= 131072) < 65536) { pk(od_whhT,          od_whh, 128, 128, w); return; }
}

// ---------------- gate GEMM, double-buffered, optionally fused LSTM cell -----
// G[m][col] = base + sum_{k<K1} A1[m*lda1+k]*WT[k][col] + sum_{k<K2} A2[m*lda2+k]*WT[K1+k][col]
// base = Rm ? Rm[m*ldr + col] : (bias ? bias[col] : 0)
// Tiles: BM=128, BN=64, BK=16, 256 threads, 8x4 per thread.
// Interleaved cols (col = 4u+g): each thread's 4 cols form one complete unit,
// so the cell update runs in the epilogue (FUSED=true). h_out must not alias
// A1/A2 (caller ping-pongs). K1 must be a multiple of 16 (or 0). K=0 with Rm
// acts as a pure cell update on Rm.
template<bool FUSED>
__global__ void __launch_bounds__(256)
gemm_k(int M, int N,
       const float* __restrict__ A1, int lda1, int K1,
       const float* __restrict__ A2, int lda2, int K2,
       const float* __restrict__ WT,
       const float* __restrict__ bias,
       const float* __restrict__ Rm, int ldr,
       float* __restrict__ G,
       float* __restrict__ c, float* __restrict__ h_out,
       float* __restrict__ rec, int rec_stride,
       int first) {
    __shared__ __align__(16) float As[2][16][132];   // As[buf][k][m]
    __shared__ __align__(16) float Bs[2][16][64];
    const int tid = threadIdx.x;
    const int bn = blockIdx.x * 64;
    const int bm = blockIdx.y * 128;
    const int tx = tid & 15;          // n group: cols tx*4..tx*4+3
    const int ty = tid >> 4;          // m group: rows ty*8..ty*8+7
    const int ar = tid & 127;         // A load row
    const int ak = (tid >> 7) << 3;   // A load k base: 0 or 8
    const int bk = tid >> 4;          // B load k row
    const int bc = (tid & 15) << 2;   // B load col

    const int K = K1 + K2;
    const int arow = bm + ar;
    const bool aok = arow < M;

    float acc[8][4];
    #pragma unroll
    for (int i = 0; i < 8; i++)
        #pragma unroll
        for (int j = 0; j < 4; j++) acc[i][j] = 0.0f;

    if (K > 0) {
        float4 pa0, pa1, pb;
        pa0 = make_float4(0.f, 0.f, 0.f, 0.f); pa1 = pa0;
        if (aok) {
            const float* p = (ak < K1) ? (A1 + (size_t)arow * lda1 + ak)
                                       : (A2 + (size_t)arow * lda2 + (ak - K1));
            pa0 = *(const float4*)p;
            pa1 = *(const float4*)(p + 4);
        }
        pb = *(const float4*)(WT + (size_t)bk * N + bn + bc);

        As[0][ak + 0][ar] = pa0.x; As[0][ak + 1][ar] = pa0.y;
        As[0][ak + 2][ar] = pa0.z; As[0][ak + 3][ar] = pa0.w;
        As[0][ak + 4][ar] = pa1.x; As[0][ak + 5][ar] = pa1.y;
        As[0][ak + 6][ar] = pa1.z; As[0][ak + 7][ar] = pa1.w;
        *(float4*)&Bs[0][bk][bc] = pb;
        __syncthreads();

        int buf = 0;
        for (int k0 = 0; k0 < K; k0 += 16, buf ^= 1) {
            const bool more = (k0 + 16) < K;
            if (more) {
                int k = k0 + 16 + ak;
                pa0 = make_float4(0.f, 0.f, 0.f, 0.f); pa1 = pa0;
                if (aok) {
                    const float* p = (k < K1) ? (A1 + (size_t)arow * lda1 + k)
                                              : (A2 + (size_t)arow * lda2 + (k - K1));
                    pa0 = *(const float4*)p;
                    pa1 = *(const float4*)(p + 4);
                }
                pb = *(const float4*)(WT + (size_t)(k0 + 16 + bk) * N + bn + bc);
            }
            #pragma unroll
            for (int k = 0; k < 16; ++k) {
                float4 a0 = *(const float4*)&As[buf][k][ty * 8];
                float4 a1 = *(const float4*)&As[buf][k][ty * 8 + 4];
                float4 b  = *(const float4*)&Bs[buf][k][tx * 4];
                float av[8] = {a0.x, a0.y, a0.z, a0.w, a1.x, a1.y, a1.z, a1.w};
                #pragma unroll
                for (int r = 0; r < 8; ++r) {
                    acc[r][0] += av[r] * b.x;
                    acc[r][1] += av[r] * b.y;
                    acc[r][2] += av[r] * b.z;
                    acc[r][3] += av[r] * b.w;
                }
            }
            if (more) {
                int nb = buf ^ 1;
                As[nb][ak + 0][ar] = pa0.x; As[nb][ak + 1][ar] = pa0.y;
                As[nb][ak + 2][ar] = pa0.z; As[nb][ak + 3][ar] = pa0.w;
                As[nb][ak + 4][ar] = pa1.x; As[nb][ak + 5][ar] = pa1.y;
                As[nb][ak + 6][ar] = pa1.z; As[nb][ak + 7][ar] = pa1.w;
                *(float4*)&Bs[nb][bk][bc] = pb;
            }
            __syncthreads();
        }
    }

    // ---- epilogue
    float4 bb = make_float4(0.f, 0.f, 0.f, 0.f);
    if (!Rm && bias) bb = *(const float4*)(bias + bn + tx * 4);
    #pragma unroll
    for (int r = 0; r < 8; ++r) {
        int row = bm + ty * 8 + r;
        if (row >= M) continue;
        float g0 = acc[r][0], g1 = acc[r][1], g2 = acc[r][2], g3 = acc[r][3];
        if (Rm) {
            float4 bv = *(const float4*)(Rm + (size_t)row * ldr + bn + tx * 4);
            g0 += bv.x; g1 += bv.y; g2 += bv.z; g3 += bv.w;
        } else {
            g0 += bb.x; g1 += bb.y; g2 += bb.z; g3 += bb.w;
        }
        if (FUSED) {
            const int Hd = N >> 2;
            const int u = (bn >> 2) + tx;
            size_t idx = (size_t)row * Hd + u;
            float cold = first ? 0.0f : c[idx];
            float cc = sigf(g1) * cold + sigf(g0) * tanhf(g2);
            c[idx] = cc;
            float hh = sigf(g3) * tanhf(cc);
            h_out[idx] = hh;
            if (rec) rec[(size_t)row * rec_stride + u] = hh;
        } else {
            *(float4*)(G + (size_t)row * N + bn + tx * 4) = make_float4(g0, g1, g2, g3);
        }
    }
}

// ---------------- persistent inner LSTM (batch 32, 1 block per sequence) ----
// xw interleaved: row layout [u*4+g]; weights interleaved float4 per (k,u).
__global__ void __launch_bounds__(256)
inner_lstm(const float* __restrict__ xw, int xw_block_stride, int xw_step_stride,
           const float4* __restrict__ wp,
           float* __restrict__ out_c, float* __restrict__ out_h, int steps) {
    __shared__ float h[HDIM];
    int b = blockIdx.x;
    int u = threadIdx.x;
    float c = 0.0f;
    h[u] = 0.0f;
    __syncthreads();
    const float* xwb = xw + (size_t)b * xw_block_stride;
    for (int s = 0; s < steps; ++s) {
        float4 xg = *reinterpret_cast<const float4*>(xwb + (u << 2));
        float g0 = xg.x, g1 = xg.y, g2 = xg.z, g3 = xg.w;
        #pragma unroll 8
        for (int k = 0; k < HDIM; ++k) {
            float hk = h[k];
            float4 w = wp[(k << 8) + u];
            g0 += hk * w.x;
            g1 += hk * w.y;
            g2 += hk * w.z;
            g3 += hk * w.w;
        }
        float cc = sigf(g1) * c + sigf(g0) * tanhf(g2);
        c = cc;
        float hh = sigf(g3) * tanhf(cc);
        __syncthreads();
        h[u] = hh;
        __syncthreads();
        if (out_h) out_h[((size_t)b * steps + s) * HDIM + u] = hh;
        xwb += xw_step_stride;
    }
    if (out_c) out_c[b * HDIM + u] = c;
}

// ---------------- host orchestration ----------------------------------------
extern "C" void kernel_launch(void* const* d_in, const int* in_sizes, int n_in,
                              void* d_out, int out_size) {
    const float* inp    = (const float*)d_in[0];
    const float* oe_wih = (const float*)d_in[1];
    const float* oe_whh = (const float*)d_in[2];
    const float* oe_bih = (const float*)d_in[3];
    const float* oe_bhh = (const float*)d_in[4];
    const float* ie_wih = (const float*)d_in[5];
    const float* ie_whh = (const float*)d_in[6];
    const float* ie_bih = (const float*)d_in[7];
    const float* ie_bhh = (const float*)d_in[8];
    const float* id_wih = (const float*)d_in[9];
    const float* id_whh = (const float*)d_in[10];
    const float* id_bih = (const float*)d_in[11];
    const float* id_bhh = (const float*)d_in[12];
    const float* od_wih = (const float*)d_in[13];
    const float* od_whh = (const float*)d_in[14];
    const float* od_bih = (const float*)d_in[15];
    const float* od_bhh = (const float*)d_in[16];
    float* out = (float*)d_out;

    void* p;
    cudaGetSymbolAddress(&p, g_xT);      float* xT      = (float*)p;
    cudaGetSymbolAddress(&p, g_rec);     float* rec     = (float*)p;
    cudaGetSymbolAddress(&p, g_xw_oe);   float* xw_oe   = (float*)p;
    cudaGetSymbolAddress(&p, g_hA);      float* hA      = (float*)p;
    cudaGetSymbolAddress(&p, g_hB);      float* hB      = (float*)p;
    cudaGetSymbolAddress(&p, g_c);       float* c1      = (float*)p;
    cudaGetSymbolAddress(&p, g_xw_ie);   float* xw_ie   = (float*)p;
    cudaGetSymbolAddress(&p, g_bot);     float* bot     = (float*)p;
    cudaGetSymbolAddress(&p, g_xw_id);   float* xw_id   = (float*)p;
    cudaGetSymbolAddress(&p, g_dec);     float* decb    = (float*)p;
    cudaGetSymbolAddress(&p, g_xw_od);   float* xw_od   = (float*)p;
    cudaGetSymbolAddress(&p, g_h2A);     float* h2A     = (float*)p;
    cudaGetSymbolAddress(&p, g_h2B);     float* h2B     = (float*)p;
    cudaGetSymbolAddress(&p, g_c2);      float* c2      = (float*)p;
    cudaGetSymbolAddress(&p, g_oe_wT);   float* oe_wT   = (float*)p;
    cudaGetSymbolAddress(&p, g_oe_b);    float* oe_b    = (float*)p;
    cudaGetSymbolAddress(&p, g_ie_wihT); float* ie_wihT = (float*)p;
    cudaGetSymbolAddress(&p, g_ie_whhI); float* ie_whhI = (float*)p;
    cudaGetSymbolAddress(&p, g_ie_b);    float* ie_b    = (float*)p;
    cudaGetSymbolAddress(&p, g_id_wihT); float* id_wihT = (float*)p;
    cudaGetSymbolAddress(&p, g_id_whhI); float* id_whhI = (float*)p;
    cudaGetSymbolAddress(&p, g_id_b);    float* id_b    = (float*)p;
    cudaGetSymbolAddress(&p, g_od_wihT); float* od_wihT = (float*)p;
    cudaGetSymbolAddress(&p, g_od_whhT); float* od_whhT = (float*)p;
    cudaGetSymbolAddress(&p, g_od_b);    float* od_b    = (float*)p;

    dim3 tb(32, 8);

    // launch 0: all packing in one kernel
    pack_all<<<6406, 256>>>(oe_wih, oe_whh, ie_wih, ie_whh, id_wih, id_whh,
                            od_wih, od_whh,
                            oe_bih, oe_bhh, ie_bih, ie_bhh, id_bih, id_bhh,
                            od_bih, od_bhh,
                            oe_wT, ie_wihT, ie_whhI, id_wihT, id_whhI,
                            od_wihT, od_whhT, oe_b, ie_b, id_b, od_b);

    // launch 1: input transpose (B,F,T) -> (B,T,F)
    btrans<<<dim3(75, 4, B_), tb>>>(xT, inp, FBINS, TTOT);

    // launch 2: hoisted oe input gates for ALL timesteps:
    // xw_oe[(b*T + s*SEG + t), 1024] = xT row * WihT + bias
    gemm_k<false><<<dim3(16, 600), 256>>>(B_ * TTOT, 1024,
                                          xT, FBINS, FBINS,
                                          nullptr, 0, 0,
                                          oe_wT, oe_b, nullptr, 0,
                                          xw_oe, nullptr, nullptr, nullptr, 0, 0);

    // launches 3..26: outer encoder recurrence, K=256 per step (step0: K=0).
    // Step t row m=(b*S+s) maps to xw_oe global row m*SEG + t.
    {
        float* hbuf[2] = { hA, hB };
        for (int t = 0; t < SEG_; ++t) {
            gemm_k<true><<<dim3(16, 25), 256>>>(BS_, 1024,
                                                hbuf[t & 1], HDIM, (t ? HDIM : 0),
                                                nullptr, 0, 0,
                                                oe_wT + 128 * 1024, nullptr,
                                                xw_oe + (size_t)t * 1024, SEG_ * 1024,
                                                nullptr, c1, hbuf[(t + 1) & 1],
                                                nullptr, 0, t == 0);
        }
    }

    // ---- inner encoder: xw precompute + persistent 100-step LSTM -> bottleneck
    gemm_k<false><<<dim3(16, 25), 256>>>(BS_, 1024, c1, HDIM, HDIM,
                                         nullptr, 0, 0, ie_wihT, ie_b, nullptr, 0,
                                         xw_ie, nullptr, nullptr, nullptr, 0, 0);
    inner_lstm<<<B_, 256>>>(xw_ie, SSEG * 1024, 1024, (const float4*)ie_whhI,
                            bot, nullptr, SSEG);

    // ---- inner decoder: constant input per step
    gemm_k<false><<<dim3(16, 1), 256>>>(B_, 1024, bot, HDIM, HDIM,
                                        nullptr, 0, 0, id_wihT, id_b, nullptr, 0,
                                        xw_id, nullptr, nullptr, nullptr, 0, 0);
    inner_lstm<<<B_, 256>>>(xw_id, 1024, 0, (const float4*)id_whhI,
                            nullptr, decb, SSEG);

    // ---- outer decoder: xw once, then 24 fused steps (writes rec directly)
    gemm_k<false><<<dim3(8, 25), 256>>>(BS_, 512, decb, HDIM, HDIM,
                                        nullptr, 0, 0, od_wihT, od_b, nullptr, 0,
                                        xw_od, nullptr, nullptr, nullptr, 0, 0);
    {
        float* hbuf[2] = { h2A, h2B };
        for (int t = 0; t < SEG_; ++t) {
            gemm_k<true><<<dim3(8, 25), 256>>>(BS_, 512,
                                               hbuf[t & 1], FBINS, (t ? FBINS : 0),
                                               nullptr, 0, 0,
                                               od_whhT, nullptr,
                                               xw_od, 512,
                                               nullptr, c2, hbuf[(t + 1) & 1],
                                               rec + t * FBINS, SEG_ * FBINS, t == 0);
        }
    }

    // ---- final transpose (B,T,F) -> (B,F,T)
    btrans<<<dim3(4, 75, B_), tb>>>(out, rec, TTOT, FBINS);
}

// round 11
// speedup vs baseline: 1.0947x; 1.0947x over previous
#include <cuda_runtime.h>
#include <math.h>

#define B_    32
#define FBINS 128
#define TTOT  2400
#define HDIM  256
#define SEG_  24
#define SSEG  100
#define BS_   3200   // B_*SSEG

// ---------------- scratch (device globals) ----------------------------------
__device__ float g_xT[B_*TTOT*FBINS];      // (B, T, F) transposed input
__device__ float g_rec[B_*TTOT*FBINS];     // (B, T, F) reconstruction
__device__ float g_xw_oe[B_*TTOT*1024];    // hoisted oe input gates (76800, 1024)
__device__ float g_c[BS_*HDIM];            // oe final cell -> c_seg
__device__ float g_xw_ie[BS_*1024];
__device__ float g_bot[B_*HDIM];           // bottleneck (final cell of ie)
__device__ float g_xw_id[B_*1024];
__device__ float g_dec[BS_*HDIM];          // inner-decoder hidden states (B,S,H)
__device__ float g_xw_od[BS_*512];
// interleaved weights (col = 4*u + g, g in {i,f,g,o}) / fused biases
__device__ float g_oe_wT[(FBINS+HDIM)*1024];   // rows 0..127: WihT, 128..383: WhhT
__device__ float g_oe_b[1024];
__device__ float g_ie_wihT[HDIM*1024];
__device__ float g_ie_whhI[HDIM*1024];
__device__ float g_ie_b[1024];
__device__ float g_id_wihT[HDIM*1024];
__device__ float g_id_whhI[HDIM*1024];
__device__ float g_id_b[1024];
__device__ float g_od_wihT[HDIM*512];
__device__ float g_od_whhT[FBINS*512];
__device__ float g_od_b[512];

__device__ __forceinline__ float sigf(float x) { return 1.0f / (1.0f + __expf(-x)); }

// ---------------- batched tiled transpose: src (batch, R, C) -> dst (batch, C, R)
__global__ void btrans(float* __restrict__ dst, const float* __restrict__ src, int R, int C) {
    __shared__ float tile[32][33];
    int b  = blockIdx.z;
    int c0 = blockIdx.x * 32, r0 = blockIdx.y * 32;
    const float* s = src + (size_t)b * R * C;
    float*       d = dst + (size_t)b * R * C;
    int tx = threadIdx.x, ty = threadIdx.y;   // 32 x 8
    #pragma unroll
    for (int i = 0; i < 32; i += 8) {
        int r = r0 + ty + i, c = c0 + tx;
        if (r < R && c < C) tile[ty + i][tx] = s[r * C + c];
    }
    __syncthreads();
    #pragma unroll
    for (int i = 0; i < 32; i += 8) {
        int c = c0 + ty + i, r = r0 + tx;
        if (c < C && r < R) d[c * R + r] = tile[tx][ty + i];
    }
}

// ---- weight interleave: dst[k*(4U) + 4u+g] = src[(g*U+u)*K + k] -------------
__device__ __forceinline__ void pk(float* __restrict__ dst, const float* __restrict__ src,
                                   int U, int K, long i) {
    int n4 = 4 * U;
    int col = (int)(i % n4);
    long k  = i / n4;
    int u = col >> 2, g = col & 3;
    dst[i] = src[(long)(g * U + u) * K + k];
}

// ---- one mega pack kernel: all biases + all interleaved weights -------------
__global__ void pack_all(const float* oe_wih, const float* oe_whh,
                         const float* ie_wih, const float* ie_whh,
                         const float* id_wih, const float* id_whh,
                         const float* od_wih, const float* od_whh,
                         const float* oe_bih, const float* oe_bhh,
                         const float* ie_bih, const float* ie_bhh,
                         const float* id_bih, const float* id_bhh,
                         const float* od_bih, const float* od_bhh,
                         float* oe_wT, float* ie_wihT, float* ie_whhI,
                         float* id_wihT, float* id_whhI,
                         float* od_wihT, float* od_whhT,
                         float* oe_b, float* ie_b, float* id_b, float* od_b) {
    long idx = (long)blockIdx.x * blockDim.x + threadIdx.x;
    if (idx < 1024) {
        int u = (int)idx >> 2, g = (int)idx & 3;
        int s = g * 256 + u;
        oe_b[idx] = oe_bih[s] + oe_bhh[s];
        ie_b[idx] = ie_bih[s] + ie_bhh[s];
        id_b[idx] = id_bih[s] + id_bhh[s];
        return;
    }
    if (idx < 1536) {
        int i = (int)idx - 1024;
        int u = i >> 2, g = i & 3;
        int s = g * 128 + u;
        od_b[i] = od_bih[s] + od_bhh[s];
        return;
    }
    long w = idx - 1536;
    if (w < 131072)            { pk(oe_wT,            oe_wih, 256, 128, w); return; }
    if ((w -= 131072) < 262144){ pk(oe_wT + 131072,   oe_whh, 256, 256, w); return; }
    if ((w -= 262144) < 262144){ pk(ie_wihT,          ie_wih, 256, 256, w); return; }
    if ((w -= 262144) < 262144){ pk(ie_whhI,          ie_whh, 256, 256, w); return; }
    if ((w -= 262144) < 262144){ pk(id_wihT,          id_wih, 256, 256, w); return; }
    if ((w -= 262144) < 262144){ pk(id_whhI,          id_whh, 256, 256, w); return; }
    if ((w -= 262144) < 131072){ pk(od_wihT,          od_wih, 128, 256, w); return; }
    if ((w -= 131072) < 65536) { pk(od_whhT,          od_whh, 128, 128, w); return; }
}

// ---------------- plain gate GEMM (for xw precomputes) -----------------------
// G[m][col] = bias[col] + sum_{k<K1} A1[m*lda1+k]*WT[k][col]
// Tiles: BM=128, BN=64, BK=16, 256 threads, 8x4 per thread, double-buffered.
__global__ void __launch_bounds__(256)
gemm_xw(int M, int N,
        const float* __restrict__ A1, int lda1, int K1,
        const float* __restrict__ WT,
        const float* __restrict__ bias,
        float* __restrict__ G) {
    __shared__ __align__(16) float As[2][16][132];
    __shared__ __align__(16) float Bs[2][16][64];
    const int tid = threadIdx.x;
    const int bn = blockIdx.x * 64;
    const int bm = blockIdx.y * 128;
    const int tx = tid & 15;
    const int ty = tid >> 4;
    const int ar = tid & 127;
    const int ak = (tid >> 7) << 3;
    const int bk = tid >> 4;
    const int bc = (tid & 15) << 2;

    const int arow = bm + ar;
    const bool aok = arow < M;

    float acc[8][4];
    #pragma unroll
    for (int i = 0; i < 8; i++)
        #pragma unroll
        for (int j = 0; j < 4; j++) acc[i][j] = 0.0f;

    float4 pa0 = make_float4(0.f,0.f,0.f,0.f), pa1 = pa0, pb;
    if (aok) {
        const float* p = A1 + (size_t)arow * lda1 + ak;
        pa0 = *(const float4*)p;
        pa1 = *(const float4*)(p + 4);
    }
    pb = *(const float4*)(WT + (size_t)bk * N + bn + bc);
    As[0][ak+0][ar]=pa0.x; As[0][ak+1][ar]=pa0.y; As[0][ak+2][ar]=pa0.z; As[0][ak+3][ar]=pa0.w;
    As[0][ak+4][ar]=pa1.x; As[0][ak+5][ar]=pa1.y; As[0][ak+6][ar]=pa1.z; As[0][ak+7][ar]=pa1.w;
    *(float4*)&Bs[0][bk][bc] = pb;
    __syncthreads();

    int buf = 0;
    for (int k0 = 0; k0 < K1; k0 += 16, buf ^= 1) {
        const bool more = (k0 + 16) < K1;
        if (more) {
            int k = k0 + 16 + ak;
            pa0 = make_float4(0.f,0.f,0.f,0.f); pa1 = pa0;
            if (aok) {
                const float* p = A1 + (size_t)arow * lda1 + k;
                pa0 = *(const float4*)p;
                pa1 = *(const float4*)(p + 4);
            }
            pb = *(const float4*)(WT + (size_t)(k0 + 16 + bk) * N + bn + bc);
        }
        #pragma unroll
        for (int k = 0; k < 16; ++k) {
            float4 a0 = *(const float4*)&As[buf][k][ty * 8];
            float4 a1 = *(const float4*)&As[buf][k][ty * 8 + 4];
            float4 b  = *(const float4*)&Bs[buf][k][tx * 4];
            float av[8] = {a0.x, a0.y, a0.z, a0.w, a1.x, a1.y, a1.z, a1.w};
            #pragma unroll
            for (int r = 0; r < 8; ++r) {
                acc[r][0] += av[r] * b.x;
                acc[r][1] += av[r] * b.y;
                acc[r][2] += av[r] * b.z;
                acc[r][3] += av[r] * b.w;
            }
        }
        if (more) {
            int nb = buf ^ 1;
            As[nb][ak+0][ar]=pa0.x; As[nb][ak+1][ar]=pa0.y; As[nb][ak+2][ar]=pa0.z; As[nb][ak+3][ar]=pa0.w;
            As[nb][ak+4][ar]=pa1.x; As[nb][ak+5][ar]=pa1.y; As[nb][ak+6][ar]=pa1.z; As[nb][ak+7][ar]=pa1.w;
            *(float4*)&Bs[nb][bk][bc] = pb;
        }
        __syncthreads();
    }

    float4 bb = *(const float4*)(bias + bn + tx * 4);
    #pragma unroll
    for (int r = 0; r < 8; ++r) {
        int row = bm + ty * 8 + r;
        if (row >= M) continue;
        *(float4*)(G + (size_t)row * N + bn + tx * 4) =
            make_float4(acc[r][0]+bb.x, acc[r][1]+bb.y, acc[r][2]+bb.z, acc[r][3]+bb.w);
    }
}

// ---------------- persistent per-sequence LSTM ------------------------------
// Each block owns ~11 independent sequences and runs ALL `steps` internally.
// h lives in smem (ping-pong), c in registers; WhhT ([HD][4*HD], interleaved
// cols 4u+g) is streamed from L2 every step.
// Thread layout: 256 threads = NRG row-groups x HD units (u = tid % HD).
// Group g handles local rows r = i*NRG + g (r can reach MAXI*NRG-1, which may
// exceed nr — those rows are compute-dead but their smem slots MUST exist and
// be zeroed: HROWS >= MAXI*NRG).
// xw_per_step=1: gate input row = m*steps + t (oe). =0: row = m, constant (od).
// Outputs: c_out (final cell, oe) and/or rec (h each step, od).
template<int HD, int NRG, int MAXI>
__global__ void __launch_bounds__(256, 2)
persistent_lstm(const float* __restrict__ xw, int xw_per_step,
                const float* __restrict__ whhT,
                float* __restrict__ c_out,
                float* __restrict__ rec,
                int steps, int M) {
    constexpr int GN = 4 * HD;
    constexpr int HROWS = MAXI * NRG;          // covers every generated row index
    __shared__ float hsm[2][HROWS][HD];
    const int tid = threadIdx.x;
    const int u = tid % HD;
    const int g = tid / HD;

    const int nb   = gridDim.x;
    const int base = M / nb;
    const int rem  = M - base * nb;
    const int bid  = blockIdx.x;
    const int nr    = base + (bid < rem ? 1 : 0);
    const int start = bid * base + (bid < rem ? bid : rem);

    float c[MAXI];
    float4 xwc[MAXI];
    #pragma unroll
    for (int i = 0; i < MAXI; i++) c[i] = 0.0f;

    // constant-input case: load xw once
    if (!xw_per_step) {
        #pragma unroll
        for (int i = 0; i < MAXI; i++) {
            int r = i * NRG + g;
            xwc[i] = (r < nr) ? *(const float4*)(xw + (size_t)(start + r) * GN + 4 * u)
                              : make_float4(0.f, 0.f, 0.f, 0.f);
        }
    }

    // zero BOTH h buffers (dead rows must stay finite/zero forever)
    for (int i = tid; i < 2 * HROWS * HD; i += 256) ((float*)hsm)[i] = 0.0f;
    __syncthreads();

    for (int t = 0; t < steps; ++t) {
        const int cur = t & 1, nxt = cur ^ 1;
        float4 acc[MAXI];
        if (xw_per_step) {
            #pragma unroll
            for (int i = 0; i < MAXI; i++) {
                int r = i * NRG + g;
                acc[i] = (r < nr)
                    ? *(const float4*)(xw + ((size_t)(start + r) * steps + t) * GN + 4 * u)
                    : make_float4(0.f, 0.f, 0.f, 0.f);
            }
        } else {
            #pragma unroll
            for (int i = 0; i < MAXI; i++) acc[i] = xwc[i];
        }
        if (t > 0) {
            #pragma unroll 4
            for (int k = 0; k < HD; ++k) {
                float4 w = *(const float4*)(whhT + (size_t)k * GN + 4 * u);
                #pragma unroll
                for (int i = 0; i < MAXI; i++) {
                    float hk = hsm[cur][i * NRG + g][k];   // broadcast LDS (in bounds: HROWS)
                    acc[i].x += hk * w.x;
                    acc[i].y += hk * w.y;
                    acc[i].z += hk * w.z;
                    acc[i].w += hk * w.w;
                }
            }
        }
        // cell update + h write
        #pragma unroll
        for (int i = 0; i < MAXI; i++) {
            int r = i * NRG + g;
            float cc = sigf(acc[i].y) * c[i] + sigf(acc[i].x) * tanhf(acc[i].z);
            c[i] = cc;
            float hh = sigf(acc[i].w) * tanhf(cc);
            if (r < nr) {
                hsm[nxt][r][u] = hh;
                if (rec) rec[((size_t)(start + r) * steps + t) * HD + u] = hh;
            }
        }
        __syncthreads();
    }

    if (c_out) {
        #pragma unroll
        for (int i = 0; i < MAXI; i++) {
            int r = i * NRG + g;
            if (r < nr) c_out[(size_t)(start + r) * HD + u] = c[i];
        }
    }
}

// ---------------- persistent inner LSTM (batch 32, 1 block per sequence) ----
// xw interleaved: row layout [u*4+g]; weights interleaved float4 per (k,u).
__global__ void __launch_bounds__(256)
inner_lstm(const float* __restrict__ xw, int xw_block_stride, int xw_step_stride,
           const float4* __restrict__ wp,
           float* __restrict__ out_c, float* __restrict__ out_h, int steps) {
    __shared__ float h[HDIM];
    int b = blockIdx.x;
    int u = threadIdx.x;
    float c = 0.0f;
    h[u] = 0.0f;
    __syncthreads();
    const float* xwb = xw + (size_t)b * xw_block_stride;
    for (int s = 0; s < steps; ++s) {
        float4 xg = *reinterpret_cast<const float4*>(xwb + (u << 2));
        float g0 = xg.x, g1 = xg.y, g2 = xg.z, g3 = xg.w;
        #pragma unroll 8
        for (int k = 0; k < HDIM; ++k) {
            float hk = h[k];
            float4 w = wp[(k << 8) + u];
            g0 += hk * w.x;
            g1 += hk * w.y;
            g2 += hk * w.z;
            g3 += hk * w.w;
        }
        float cc = sigf(g1) * c + sigf(g0) * tanhf(g2);
        c = cc;
        float hh = sigf(g3) * tanhf(cc);
        __syncthreads();
        h[u] = hh;
        __syncthreads();
        if (out_h) out_h[((size_t)b * steps + s) * HDIM + u] = hh;
        xwb += xw_step_stride;
    }
    if (out_c) out_c[b * HDIM + u] = c;
}

// ---------------- host orchestration ----------------------------------------
extern "C" void kernel_launch(void* const* d_in, const int* in_sizes, int n_in,
                              void* d_out, int out_size) {
    const float* inp    = (const float*)d_in[0];
    const float* oe_wih = (const float*)d_in[1];
    const float* oe_whh = (const float*)d_in[2];
    const float* oe_bih = (const float*)d_in[3];
    const float* oe_bhh = (const float*)d_in[4];
    const float* ie_wih = (const float*)d_in[5];
    const float* ie_whh = (const float*)d_in[6];
    const float* ie_bih = (const float*)d_in[7];
    const float* ie_bhh = (const float*)d_in[8];
    const float* id_wih = (const float*)d_in[9];
    const float* id_whh = (const float*)d_in[10];
    const float* id_bih = (const float*)d_in[11];
    const float* id_bhh = (const float*)d_in[12];
    const float* od_wih = (const float*)d_in[13];
    const float* od_whh = (const float*)d_in[14];
    const float* od_bih = (const float*)d_in[15];
    const float* od_bhh = (const float*)d_in[16];
    float* out = (float*)d_out;

    void* p;
    cudaGetSymbolAddress(&p, g_xT);      float* xT      = (float*)p;
    cudaGetSymbolAddress(&p, g_rec);     float* rec     = (float*)p;
    cudaGetSymbolAddress(&p, g_xw_oe);   float* xw_oe   = (float*)p;
    cudaGetSymbolAddress(&p, g_c);       float* c1      = (float*)p;
    cudaGetSymbolAddress(&p, g_xw_ie);   float* xw_ie   = (float*)p;
    cudaGetSymbolAddress(&p, g_bot);     float* bot     = (float*)p;
    cudaGetSymbolAddress(&p, g_xw_id);   float* xw_id   = (float*)p;
    cudaGetSymbolAddress(&p, g_dec);     float* decb    = (float*)p;
    cudaGetSymbolAddress(&p, g_xw_od);   float* xw_od   = (float*)p;
    cudaGetSymbolAddress(&p, g_oe_wT);   float* oe_wT   = (float*)p;
    cudaGetSymbolAddress(&p, g_oe_b);    float* oe_b    = (float*)p;
    cudaGetSymbolAddress(&p, g_ie_wihT); float* ie_wihT = (float*)p;
    cudaGetSymbolAddress(&p, g_ie_whhI); float* ie_whhI = (float*)p;
    cudaGetSymbolAddress(&p, g_ie_b);    float* ie_b    = (float*)p;
    cudaGetSymbolAddress(&p, g_id_wihT); float* id_wihT = (float*)p;
    cudaGetSymbolAddress(&p, g_id_whhI); float* id_whhI = (float*)p;
    cudaGetSymbolAddress(&p, g_id_b);    float* id_b    = (float*)p;
    cudaGetSymbolAddress(&p, g_od_wihT); float* od_wihT = (float*)p;
    cudaGetSymbolAddress(&p, g_od_whhT); float* od_whhT = (float*)p;
    cudaGetSymbolAddress(&p, g_od_b);    float* od_b    = (float*)p;

    dim3 tb(32, 8);

    // 0: all packing in one kernel
    pack_all<<<6406, 256>>>(oe_wih, oe_whh, ie_wih, ie_whh, id_wih, id_whh,
                            od_wih, od_whh,
                            oe_bih, oe_bhh, ie_bih, ie_bhh, id_bih, id_bhh,
                            od_bih, od_bhh,
                            oe_wT, ie_wihT, ie_whhI, id_wihT, id_whhI,
                            od_wihT, od_whhT, oe_b, ie_b, id_b, od_b);

    // 1: input transpose (B,F,T) -> (B,T,F)
    btrans<<<dim3(75, 4, B_), tb>>>(xT, inp, FBINS, TTOT);

    // 2: hoisted oe input gates for ALL timesteps (fully parallel)
    gemm_xw<<<dim3(16, 600), 256>>>(B_ * TTOT, 1024, xT, FBINS, FBINS,
                                    oe_wT, oe_b, xw_oe);

    // 3: outer encoder — persistent, 24 steps in-kernel, final c -> c1
    persistent_lstm<256, 1, 11><<<296, 256>>>(xw_oe, 1, oe_wT + 128 * 1024,
                                              c1, nullptr, SEG_, BS_);

    // 4: inner encoder xw precompute
    gemm_xw<<<dim3(16, 25), 256>>>(BS_, 1024, c1, HDIM, HDIM, ie_wihT, ie_b, xw_ie);
    // 5: inner encoder (100 steps) -> bottleneck
    inner_lstm<<<B_, 256>>>(xw_ie, SSEG * 1024, 1024, (const float4*)ie_whhI,
                            bot, nullptr, SSEG);

    // 6: inner decoder xw (constant input per step)
    gemm_xw<<<dim3(16, 1), 256>>>(B_, 1024, bot, HDIM, HDIM, id_wihT, id_b, xw_id);
    // 7: inner decoder (100 steps) -> dec hidden states
    inner_lstm<<<B_, 256>>>(xw_id, 1024, 0, (const float4*)id_whhI,
                            nullptr, decb, SSEG);

    // 8: outer decoder xw (constant per segment)
    gemm_xw<<<dim3(8, 25), 256>>>(BS_, 512, decb, HDIM, HDIM, od_wihT, od_b, xw_od);
    // 9: outer decoder — persistent, 24 steps, h -> rec each step
    persistent_lstm<128, 2, 6><<<296, 256>>>(xw_od, 0, od_whhT,
                                             nullptr, rec, SEG_, BS_);

    // 10: final transpose (B,T,F) -> (B,F,T)
    btrans<<<dim3(4, 75, B_), tb>>>(out, rec, TTOT, FBINS);
}

// round 15
// speedup vs baseline: 1.1223x; 1.0252x over previous
#include <cuda_runtime.h>
#include <math.h>

#define B_    32
#define FBINS 128
#define TTOT  2400
#define HDIM  256
#define SEG_  24
#define SSEG  100
#define BS_   3200   // B_*SSEG

// ---------------- scratch (device globals) ----------------------------------
__device__ float g_xT[B_*TTOT*FBINS];      // (B, T, F) transposed input
__device__ float g_rec[B_*TTOT*FBINS];     // (B, T, F) reconstruction
__device__ float g_xw_oe[B_*TTOT*1024];    // hoisted oe input gates (76800, 1024)
__device__ float g_c[BS_*HDIM];            // oe final cell -> c_seg
__device__ float g_xw_ie[BS_*1024];
__device__ float g_bot[B_*HDIM];           // bottleneck (final cell of ie)
__device__ float g_xw_id[B_*1024];
__device__ float g_dec[BS_*HDIM];          // inner-decoder hidden states (B,S,H)
__device__ float g_xw_od[BS_*512];
// interleaved weights (col = 4*u + g, g in {i,f,g,o}) / fused biases
__device__ float g_oe_wT[(FBINS+HDIM)*1024];   // rows 0..127: WihT, 128..383: WhhT
__device__ float g_oe_b[1024];
__device__ float g_ie_wihT[HDIM*1024];
__device__ float g_ie_whhI[HDIM*1024];
__device__ float g_ie_b[1024];
__device__ float g_id_wihT[HDIM*1024];
__device__ float g_id_whhI[HDIM*1024];
__device__ float g_id_b[1024];
__device__ float g_od_wihT[HDIM*512];
__device__ float g_od_whhT[FBINS*512];
__device__ float g_od_b[512];

__device__ __forceinline__ float sigf(float x) { return 1.0f / (1.0f + __expf(-x)); }

// ---------------- batched tiled transpose: src (batch, R, C) -> dst (batch, C, R)
__global__ void btrans(float* __restrict__ dst, const float* __restrict__ src, int R, int C) {
    __shared__ float tile[32][33];
    int b  = blockIdx.z;
    int c0 = blockIdx.x * 32, r0 = blockIdx.y * 32;
    const float* s = src + (size_t)b * R * C;
    float*       d = dst + (size_t)b * R * C;
    int tx = threadIdx.x, ty = threadIdx.y;   // 32 x 8
    #pragma unroll
    for (int i = 0; i < 32; i += 8) {
        int r = r0 + ty + i, c = c0 + tx;
        if (r < R && c < C) tile[ty + i][tx] = s[r * C + c];
    }
    __syncthreads();
    #pragma unroll
    for (int i = 0; i < 32; i += 8) {
        int c = c0 + ty + i, r = r0 + tx;
        if (c < C && r < R) d[c * R + r] = tile[tx][ty + i];
    }
}

// ---- weight interleave: dst[k*(4U) + 4u+g] = src[(g*U+u)*K + k] -------------
__device__ __forceinline__ void pk(float* __restrict__ dst, const float* __restrict__ src,
                                   int U, int K, long i) {
    int n4 = 4 * U;
    int col = (int)(i % n4);
    long k  = i / n4;
    int u = col >> 2, g = col & 3;
    dst[i] = src[(long)(g * U + u) * K + k];
}

// ---- one mega pack kernel: all biases + all interleaved weights -------------
__global__ void pack_all(const float* oe_wih, const float* oe_whh,
                         const float* ie_wih, const float* ie_whh,
                         const float* id_wih, const float* id_whh,
                         const float* od_wih, const float* od_whh,
                         const float* oe_bih, const float* oe_bhh,
                         const float* ie_bih, const float* ie_bhh,
                         const float* id_bih, const float* id_bhh,
                         const float* od_bih, const float* od_bhh,
                         float* oe_wT, float* ie_wihT, float* ie_whhI,
                         float* id_wihT, float* id_whhI,
                         float* od_wihT, float* od_whhT,
                         float* oe_b, float* ie_b, float* id_b, float* od_b) {
    long idx = (long)blockIdx.x * blockDim.x + threadIdx.x;
    if (idx < 1024) {
        int u = (int)idx >> 2, g = (int)idx & 3;
        int s = g * 256 + u;
        oe_b[idx] = oe_bih[s] + oe_bhh[s];
        ie_b[idx] = ie_bih[s] + ie_bhh[s];
        id_b[idx] = id_bih[s] + id_bhh[s];
        return;
    }
    if (idx < 1536) {
        int i = (int)idx - 1024;
        int u = i >> 2, g = i & 3;
        int s = g * 128 + u;
        od_b[i] = od_bih[s] + od_bhh[s];
        return;
    }
    long w = idx - 1536;
    if (w < 131072)            { pk(oe_wT,            oe_wih, 256, 128, w); return; }
    if ((w -= 131072) < 262144){ pk(oe_wT + 131072,   oe_whh, 256, 256, w); return; }
    if ((w -= 262144) < 262144){ pk(ie_wihT,          ie_wih, 256, 256, w); return; }
    if ((w -= 262144) < 262144){ pk(ie_whhI,          ie_whh, 256, 256, w); return; }
    if ((w -= 262144) < 262144){ pk(id_wihT,          id_wih, 256, 256, w); return; }
    if ((w -= 262144) < 262144){ pk(id_whhI,          id_whh, 256, 256, w); return; }
    if ((w -= 262144) < 131072){ pk(od_wihT,          od_wih, 128, 256, w); return; }
    if ((w -= 131072) < 65536) { pk(od_whhT,          od_whh, 128, 128, w); return; }
}

// ---------------- plain gate GEMM (for xw precomputes) -----------------------
// G[m][col] = bias[col] + sum_{k<K1} A1[m*lda1+k]*WT[k][col]
// Tiles: BM=128, BN=64, BK=16, 256 threads, 8x4 per thread, double-buffered.
__global__ void __launch_bounds__(256)
gemm_xw(int M, int N,
        const float* __restrict__ A1, int lda1, int K1,
        const float* __restrict__ WT,
        const float* __restrict__ bias,
        float* __restrict__ G) {
    __shared__ __align__(16) float As[2][16][132];
    __shared__ __align__(16) float Bs[2][16][64];
    const int tid = threadIdx.x;
    const int bn = blockIdx.x * 64;
    const int bm = blockIdx.y * 128;
    const int tx = tid & 15;
    const int ty = tid >> 4;
    const int ar = tid & 127;
    const int ak = (tid >> 7) << 3;
    const int bk = tid >> 4;
    const int bc = (tid & 15) << 2;

    const int arow = bm + ar;
    const bool aok = arow < M;

    float acc[8][4];
    #pragma unroll
    for (int i = 0; i < 8; i++)
        #pragma unroll
        for (int j = 0; j < 4; j++) acc[i][j] = 0.0f;

    float4 pa0 = make_float4(0.f,0.f,0.f,0.f), pa1 = pa0, pb;
    if (aok) {
        const float* p = A1 + (size_t)arow * lda1 + ak;
        pa0 = *(const float4*)p;
        pa1 = *(const float4*)(p + 4);
    }
    pb = *(const float4*)(WT + (size_t)bk * N + bn + bc);
    As[0][ak+0][ar]=pa0.x; As[0][ak+1][ar]=pa0.y; As[0][ak+2][ar]=pa0.z; As[0][ak+3][ar]=pa0.w;
    As[0][ak+4][ar]=pa1.x; As[0][ak+5][ar]=pa1.y; As[0][ak+6][ar]=pa1.z; As[0][ak+7][ar]=pa1.w;
    *(float4*)&Bs[0][bk][bc] = pb;
    __syncthreads();

    int buf = 0;
    for (int k0 = 0; k0 < K1; k0 += 16, buf ^= 1) {
        const bool more = (k0 + 16) < K1;
        if (more) {
            int k = k0 + 16 + ak;
            pa0 = make_float4(0.f,0.f,0.f,0.f); pa1 = pa0;
            if (aok) {
                const float* p = A1 + (size_t)arow * lda1 + k;
                pa0 = *(const float4*)p;
                pa1 = *(const float4*)(p + 4);
            }
            pb = *(const float4*)(WT + (size_t)(k0 + 16 + bk) * N + bn + bc);
        }
        #pragma unroll
        for (int k = 0; k < 16; ++k) {
            float4 a0 = *(const float4*)&As[buf][k][ty * 8];
            float4 a1 = *(const float4*)&As[buf][k][ty * 8 + 4];
            float4 b  = *(const float4*)&Bs[buf][k][tx * 4];
            float av[8] = {a0.x, a0.y, a0.z, a0.w, a1.x, a1.y, a1.z, a1.w};
            #pragma unroll
            for (int r = 0; r < 8; ++r) {
                acc[r][0] += av[r] * b.x;
                acc[r][1] += av[r] * b.y;
                acc[r][2] += av[r] * b.z;
                acc[r][3] += av[r] * b.w;
            }
        }
        if (more) {
            int nb = buf ^ 1;
            As[nb][ak+0][ar]=pa0.x; As[nb][ak+1][ar]=pa0.y; As[nb][ak+2][ar]=pa0.z; As[nb][ak+3][ar]=pa0.w;
            As[nb][ak+4][ar]=pa1.x; As[nb][ak+5][ar]=pa1.y; As[nb][ak+6][ar]=pa1.z; As[nb][ak+7][ar]=pa1.w;
            *(float4*)&Bs[nb][bk][bc] = pb;
        }
        __syncthreads();
    }

    float4 bb = *(const float4*)(bias + bn + tx * 4);
    #pragma unroll
    for (int r = 0; r < 8; ++r) {
        int row = bm + ty * 8 + r;
        if (row >= M) continue;
        *(float4*)(G + (size_t)row * N + bn + tx * 4) =
            make_float4(acc[r][0]+bb.x, acc[r][1]+bb.y, acc[r][2]+bb.z, acc[r][3]+bb.w);
    }
}

// ---------------- persistent per-sequence LSTM ------------------------------
// Each block owns ~MAXI sequences and runs ALL `steps` internally.
// h in smem (ping-pong), c in registers; WhhT ([HD][4*HD], interleaved cols
// 4u+g) streamed from L2 every step with a 4-k register double-buffer so the
// LDG latency is hidden behind the previous chunk's FFMAs.
// Thread layout: 256 threads = NRG row-groups x HD units (u = tid % HD).
// Group g handles local rows r = i*NRG + g; HROWS >= MAXI*NRG keeps every
// generated smem row index in bounds (dead rows stay zero).
// xw_per_step=1: gate input row = m*steps + t (oe). =0: row = m, constant (od).
template<int HD, int NRG, int MAXI>
__global__ void __launch_bounds__(256, 2)
persistent_lstm(const float* __restrict__ xw, int xw_per_step,
                const float* __restrict__ whhT,
                float* __restrict__ c_out,
                float* __restrict__ rec,
                int steps, int M) {
    constexpr int GN = 4 * HD;
    constexpr int HROWS = MAXI * NRG;
    __shared__ float hsm[2][HROWS][HD];
    const int tid = threadIdx.x;
    const int u = tid % HD;
    const int g = tid / HD;

    const int nb   = gridDim.x;
    const int base = M / nb;
    const int rem  = M - base * nb;
    const int bid  = blockIdx.x;
    const int nr    = base + (bid < rem ? 1 : 0);
    const int start = bid * base + (bid < rem ? bid : rem);

    float c[MAXI];
    float4 xwc[MAXI];
    #pragma unroll
    for (int i = 0; i < MAXI; i++) c[i] = 0.0f;

    if (!xw_per_step) {
        #pragma unroll
        for (int i = 0; i < MAXI; i++) {
            int r = i * NRG + g;
            xwc[i] = (r < nr) ? *(const float4*)(xw + (size_t)(start + r) * GN + 4 * u)
                              : make_float4(0.f, 0.f, 0.f, 0.f);
        }
    }

    // zero BOTH h buffers
    for (int i = tid; i < 2 * HROWS * HD; i += 256) ((float*)hsm)[i] = 0.0f;
    __syncthreads();

    const float* wbase = whhT + 4 * u;   // column for this thread

    for (int t = 0; t < steps; ++t) {
        const int cur = t & 1, nxt = cur ^ 1;
        float4 acc[MAXI];
        if (xw_per_step) {
            #pragma unroll
            for (int i = 0; i < MAXI; i++) {
                int r = i * NRG + g;
                acc[i] = (r < nr)
                    ? *(const float4*)(xw + ((size_t)(start + r) * steps + t) * GN + 4 * u)
                    : make_float4(0.f, 0.f, 0.f, 0.f);
            }
        } else {
            #pragma unroll
            for (int i = 0; i < MAXI; i++) acc[i] = xwc[i];
        }
        if (t > 0) {
            // prologue: chunk 0 weights
            float4 wc0 = *(const float4*)(wbase + 0 * GN);
            float4 wc1 = *(const float4*)(wbase + 1 * GN);
            float4 wc2 = *(const float4*)(wbase + 2 * GN);
            float4 wc3 = *(const float4*)(wbase + 3 * GN);
            for (int k0 = 0; k0 < HD; k0 += 4) {
                // prefetch next chunk's weights (hidden under this chunk's FFMAs)
                float4 wn0, wn1, wn2, wn3;
                if (k0 + 4 < HD) {
                    const float* wp = wbase + (size_t)(k0 + 4) * GN;
                    wn0 = *(const float4*)(wp + 0 * GN);
                    wn1 = *(const float4*)(wp + 1 * GN);
                    wn2 = *(const float4*)(wp + 2 * GN);
                    wn3 = *(const float4*)(wp + 3 * GN);
                }
                #pragma unroll
                for (int i = 0; i < MAXI; i++) {
                    float4 h4 = *(const float4*)&hsm[cur][i * NRG + g][k0];  // LDS.128 bcast
                    acc[i].x += h4.x * wc0.x; acc[i].y += h4.x * wc0.y;
                    acc[i].z += h4.x * wc0.z; acc[i].w += h4.x * wc0.w;
                    acc[i].x += h4.y * wc1.x; acc[i].y += h4.y * wc1.y;
                    acc[i].z += h4.y * wc1.z; acc[i].w += h4.y * wc1.w;
                    acc[i].x += h4.z * wc2.x; acc[i].y += h4.z * wc2.y;
                    acc[i].z += h4.z * wc2.z; acc[i].w += h4.z * wc2.w;
                    acc[i].x += h4.w * wc3.x; acc[i].y += h4.w * wc3.y;
                    acc[i].z += h4.w * wc3.z; acc[i].w += h4.w * wc3.w;
                }
                if (k0 + 4 < HD) { wc0 = wn0; wc1 = wn1; wc2 = wn2; wc3 = wn3; }
            }
        }
        // cell update + h write
        #pragma unroll
        for (int i = 0; i < MAXI; i++) {
            int r = i * NRG + g;
            float cc = sigf(acc[i].y) * c[i] + sigf(acc[i].x) * tanhf(acc[i].z);
            c[i] = cc;
            float hh = sigf(acc[i].w) * tanhf(cc);
            if (r < nr) {
                hsm[nxt][r][u] = hh;
                if (rec) rec[((size_t)(start + r) * steps + t) * HD + u] = hh;
            }
        }
        __syncthreads();
    }

    if (c_out) {
        #pragma unroll
        for (int i = 0; i < MAXI; i++) {
            int r = i * NRG + g;
            if (r < nr) c_out[(size_t)(start + r) * HD + u] = c[i];
        }
    }
}

// ---------------- persistent inner LSTM (batch 32, 1 block per sequence) ----
// xw interleaved: row layout [u*4+g]; weights interleaved float4 per (k,u).
__global__ void __launch_bounds__(256)
inner_lstm(const float* __restrict__ xw, int xw_block_stride, int xw_step_stride,
           const float4* __restrict__ wp,
           float* __restrict__ out_c, float* __restrict__ out_h, int steps) {
    __shared__ float h[HDIM];
    int b = blockIdx.x;
    int u = threadIdx.x;
    float c = 0.0f;
    h[u] = 0.0f;
    __syncthreads();
    const float* xwb = xw + (size_t)b * xw_block_stride;
    for (int s = 0; s < steps; ++s) {
        float4 xg = *reinterpret_cast<const float4*>(xwb + (u << 2));
        float g0 = xg.x, g1 = xg.y, g2 = xg.z, g3 = xg.w;
        #pragma unroll 8
        for (int k = 0; k < HDIM; ++k) {
            float hk = h[k];
            float4 w = wp[(k << 8) + u];
            g0 += hk * w.x;
            g1 += hk * w.y;
            g2 += hk * w.z;
            g3 += hk * w.w;
        }
        float cc = sigf(g1) * c + sigf(g0) * tanhf(g2);
        c = cc;
        float hh = sigf(g3) * tanhf(cc);
        __syncthreads();
        h[u] = hh;
        __syncthreads();
        if (out_h) out_h[((size_t)b * steps + s) * HDIM + u] = hh;
        xwb += xw_step_stride;
    }
    if (out_c) out_c[b * HDIM + u] = c;
}

// ---------------- host orchestration ----------------------------------------
extern "C" void kernel_launch(void* const* d_in, const int* in_sizes, int n_in,
                              void* d_out, int out_size) {
    const float* inp    = (const float*)d_in[0];
    const float* oe_wih = (const float*)d_in[1];
    const float* oe_whh = (const float*)d_in[2];
    const float* oe_bih = (const float*)d_in[3];
    const float* oe_bhh = (const float*)d_in[4];
    const float* ie_wih = (const float*)d_in[5];
    const float* ie_whh = (const float*)d_in[6];
    const float* ie_bih = (const float*)d_in[7];
    const float* ie_bhh = (const float*)d_in[8];
    const float* id_wih = (const float*)d_in[9];
    const float* id_whh = (const float*)d_in[10];
    const float* id_bih = (const float*)d_in[11];
    const float* id_bhh = (const float*)d_in[12];
    const float* od_wih = (const float*)d_in[13];
    const float* od_whh = (const float*)d_in[14];
    const float* od_bih = (const float*)d_in[15];
    const float* od_bhh = (const float*)d_in[16];
    float* out = (float*)d_out;

    void* p;
    cudaGetSymbolAddress(&p, g_xT);      float* xT      = (float*)p;
    cudaGetSymbolAddress(&p, g_rec);     float* rec     = (float*)p;
    cudaGetSymbolAddress(&p, g_xw_oe);   float* xw_oe   = (float*)p;
    cudaGetSymbolAddress(&p, g_c);       float* c1      = (float*)p;
    cudaGetSymbolAddress(&p, g_xw_ie);   float* xw_ie   = (float*)p;
    cudaGetSymbolAddress(&p, g_bot);     float* bot     = (float*)p;
    cudaGetSymbolAddress(&p, g_xw_id);   float* xw_id   = (float*)p;
    cudaGetSymbolAddress(&p, g_dec);     float* decb    = (float*)p;
    cudaGetSymbolAddress(&p, g_xw_od);   float* xw_od   = (float*)p;
    cudaGetSymbolAddress(&p, g_oe_wT);   float* oe_wT   = (float*)p;
    cudaGetSymbolAddress(&p, g_oe_b);    float* oe_b    = (float*)p;
    cudaGetSymbolAddress(&p, g_ie_wihT); float* ie_wihT = (float*)p;
    cudaGetSymbolAddress(&p, g_ie_whhI); float* ie_whhI = (float*)p;
    cudaGetSymbolAddress(&p, g_ie_b);    float* ie_b    = (float*)p;
    cudaGetSymbolAddress(&p, g_id_wihT); float* id_wihT = (float*)p;
    cudaGetSymbolAddress(&p, g_id_whhI); float* id_whhI = (float*)p;
    cudaGetSymbolAddress(&p, g_id_b);    float* id_b    = (float*)p;
    cudaGetSymbolAddress(&p, g_od_wihT); float* od_wihT = (float*)p;
    cudaGetSymbolAddress(&p, g_od_whhT); float* od_whhT = (float*)p;
    cudaGetSymbolAddress(&p, g_od_b);    float* od_b    = (float*)p;

    dim3 tb(32, 8);

    // 0: all packing in one kernel
    pack_all<<<6406, 256>>>(oe_wih, oe_whh, ie_wih, ie_whh, id_wih, id_whh,
                            od_wih, od_whh,
                            oe_bih, oe_bhh, ie_bih, ie_bhh, id_bih, id_bhh,
                            od_bih, od_bhh,
                            oe_wT, ie_wihT, ie_whhI, id_wihT, id_whhI,
                            od_wihT, od_whhT, oe_b, ie_b, id_b, od_b);

    // 1: input transpose (B,F,T) -> (B,T,F)
    btrans<<<dim3(75, 4, B_), tb>>>(xT, inp, FBINS, TTOT);

    // 2: hoisted oe input gates for ALL timesteps (fully parallel)
    gemm_xw<<<dim3(16, 600), 256>>>(B_ * TTOT, 1024, xT, FBINS, FBINS,
                                    oe_wT, oe_b, xw_oe);

    // 3: outer encoder — persistent, 24 steps in-kernel, final c -> c1
    persistent_lstm<256, 1, 11><<<296, 256>>>(xw_oe, 1, oe_wT + 128 * 1024,
                                              c1, nullptr, SEG_, BS_);

    // 4: inner encoder xw precompute
    gemm_xw<<<dim3(16, 25), 256>>>(BS_, 1024, c1, HDIM, HDIM, ie_wihT, ie_b, xw_ie);
    // 5: inner encoder (100 steps) -> bottleneck
    inner_lstm<<<B_, 256>>>(xw_ie, SSEG * 1024, 1024, (const float4*)ie_whhI,
                            bot, nullptr, SSEG);

    // 6: inner decoder xw (constant input per step)
    gemm_xw<<<dim3(16, 1), 256>>>(B_, 1024, bot, HDIM, HDIM, id_wihT, id_b, xw_id);
    // 7: inner decoder (100 steps) -> dec hidden states
    inner_lstm<<<B_, 256>>>(xw_id, 1024, 0, (const float4*)id_whhI,
                            nullptr, decb, SSEG);

    // 8: outer decoder xw (constant per segment)
    gemm_xw<<<dim3(8, 25), 256>>>(BS_, 512, decb, HDIM, HDIM, od_wihT, od_b, xw_od);
    // 9: outer decoder — persistent, 24 steps, h -> rec each step
    persistent_lstm<128, 2, 6><<<296, 256>>>(xw_od, 0, od_whhT,
                                             nullptr, rec, SEG_, BS_);

    // 10: final transpose (B,T,F) -> (B,F,T)
    btrans<<<dim3(4, 75, B_), tb>>>(out, rec, TTOT, FBINS);
}

// round 17
// speedup vs baseline: 1.1711x; 1.0435x over previous
#include <cuda_runtime.h>
#include <math.h>

#define B_    32
#define FBINS 128
#define TTOT  2400
#define HDIM  256
#define SEG_  24
#define SSEG  100
#define BS_   3200   // B_*SSEG

// ---------------- scratch (device globals) ----------------------------------
__device__ float g_xT[B_*TTOT*FBINS];      // (B, T, F) transposed input
__device__ float g_rec[B_*TTOT*FBINS];     // (B, T, F) reconstruction
__device__ float g_xw_oe[B_*TTOT*1024];    // hoisted oe input gates (76800, 1024)
__device__ float g_c[BS_*HDIM];            // oe final cell -> c_seg
__device__ float g_xw_ie[BS_*1024];
__device__ float g_bot[B_*HDIM];           // bottleneck (final cell of ie)
__device__ float g_xw_id[B_*1024];
__device__ float g_dec[BS_*HDIM];          // inner-decoder hidden states (B,S,H)
__device__ float g_xw_od[BS_*512];
// interleaved weights (col = 4*u + g, g in {i,f,g,o}) / fused biases
__device__ float g_oe_wT[(FBINS+HDIM)*1024];   // rows 0..127: WihT, 128..383: WhhT
__device__ float g_oe_b[1024];
__device__ float g_ie_wihT[HDIM*1024];
__device__ float g_ie_whhI[HDIM*1024];
__device__ float g_ie_b[1024];
__device__ float g_id_wihT[HDIM*1024];
__device__ float g_id_whhI[HDIM*1024];
__device__ float g_id_b[1024];
__device__ float g_od_wihT[HDIM*512];
__device__ float g_od_whhT[FBINS*512];
__device__ float g_od_b[512];

// fast sigmoid: MUFU.EX2 + MUFU.RCP path (~1e-6 abs err, safe at ±inf)
__device__ __forceinline__ float sigf(float x) {
    return __fdividef(1.0f, 1.0f + __expf(-x));
}
// fast tanh via 2*sigma(2x)-1 (~1e-6 abs err; exact limits at ±inf)
__device__ __forceinline__ float tanh_f(float x) {
    return __fdividef(2.0f, 1.0f + __expf(-2.0f * x)) - 1.0f;
}

// ---------------- batched tiled transpose: src (batch, R, C) -> dst (batch, C, R)
__global__ void btrans(float* __restrict__ dst, const float* __restrict__ src, int R, int C) {
    __shared__ float tile[32][33];
    int b  = blockIdx.z;
    int c0 = blockIdx.x * 32, r0 = blockIdx.y * 32;
    const float* s = src + (size_t)b * R * C;
    float*       d = dst + (size_t)b * R * C;
    int tx = threadIdx.x, ty = threadIdx.y;   // 32 x 8
    #pragma unroll
    for (int i = 0; i < 32; i += 8) {
        int r = r0 + ty + i, c = c0 + tx;
        if (r < R && c < C) tile[ty + i][tx] = s[r * C + c];
    }
    __syncthreads();
    #pragma unroll
    for (int i = 0; i < 32; i += 8) {
        int c = c0 + ty + i, r = r0 + tx;
        if (c < C && r < R) d[c * R + r] = tile[tx][ty + i];
    }
}

// ---- weight interleave: dst[k*(4U) + 4u+g] = src[(g*U+u)*K + k] -------------
__device__ __forceinline__ void pk(float* __restrict__ dst, const float* __restrict__ src,
                                   int U, int K, long i) {
    int n4 = 4 * U;
    int col = (int)(i % n4);
    long k  = i / n4;
    int u = col >> 2, g = col & 3;
    dst[i] = src[(long)(g * U + u) * K + k];
}

// ---- one mega pack kernel: all biases + all interleaved weights -------------
__global__ void pack_all(const float* oe_wih, const float* oe_whh,
                         const float* ie_wih, const float* ie_whh,
                         const float* id_wih, const float* id_whh,
                         const float* od_wih, const float* od_whh,
                         const float* oe_bih, const float* oe_bhh,
                         const float* ie_bih, const float* ie_bhh,
                         const float* id_bih, const float* id_bhh,
                         const float* od_bih, const float* od_bhh,
                         float* oe_wT, float* ie_wihT, float* ie_whhI,
                         float* id_wihT, float* id_whhI,
                         float* od_wihT, float* od_whhT,
                         float* oe_b, float* ie_b, float* id_b, float* od_b) {
    long idx = (long)blockIdx.x * blockDim.x + threadIdx.x;
    if (idx < 1024) {
        int u = (int)idx >> 2, g = (int)idx & 3;
        int s = g * 256 + u;
        oe_b[idx] = oe_bih[s] + oe_bhh[s];
        ie_b[idx] = ie_bih[s] + ie_bhh[s];
        id_b[idx] = id_bih[s] + id_bhh[s];
        return;
    }
    if (idx < 1536) {
        int i = (int)idx - 1024;
        int u = i >> 2, g = i & 3;
        int s = g * 128 + u;
        od_b[i] = od_bih[s] + od_bhh[s];
        return;
    }
    long w = idx - 1536;
    if (w < 131072)            { pk(oe_wT,            oe_wih, 256, 128, w); return; }
    if ((w -= 131072) < 262144){ pk(oe_wT + 131072,   oe_whh, 256, 256, w); return; }
    if ((w -= 262144) < 262144){ pk(ie_wihT,          ie_wih, 256, 256, w); return; }
    if ((w -= 262144) < 262144){ pk(ie_whhI,          ie_whh, 256, 256, w); return; }
    if ((w -= 262144) < 262144){ pk(id_wihT,          id_wih, 256, 256, w); return; }
    if ((w -= 262144) < 262144){ pk(id_whhI,          id_whh, 256, 256, w); return; }
    if ((w -= 262144) < 131072){ pk(od_wihT,          od_wih, 128, 256, w); return; }
    if ((w -= 131072) < 65536) { pk(od_whhT,          od_whh, 128, 128, w); return; }
}

// ---------------- plain gate GEMM (for xw precomputes) -----------------------
// G[m][col] = bias[col] + sum_{k<K1} A1[m*lda1+k]*WT[k][col]
// Tiles: BM=128, BN=64, BK=16, 256 threads, 8x4 per thread, double-buffered.
__global__ void __launch_bounds__(256)
gemm_xw(int M, int N,
        const float* __restrict__ A1, int lda1, int K1,
        const float* __restrict__ WT,
        const float* __restrict__ bias,
        float* __restrict__ G) {
    __shared__ __align__(16) float As[2][16][132];
    __shared__ __align__(16) float Bs[2][16][64];
    const int tid = threadIdx.x;
    const int bn = blockIdx.x * 64;
    const int bm = blockIdx.y * 128;
    const int tx = tid & 15;
    const int ty = tid >> 4;
    const int ar = tid & 127;
    const int ak = (tid >> 7) << 3;
    const int bk = tid >> 4;
    const int bc = (tid & 15) << 2;

    const int arow = bm + ar;
    const bool aok = arow < M;

    float acc[8][4];
    #pragma unroll
    for (int i = 0; i < 8; i++)
        #pragma unroll
        for (int j = 0; j < 4; j++) acc[i][j] = 0.0f;

    float4 pa0 = make_float4(0.f,0.f,0.f,0.f), pa1 = pa0, pb;
    if (aok) {
        const float* p = A1 + (size_t)arow * lda1 + ak;
        pa0 = *(const float4*)p;
        pa1 = *(const float4*)(p + 4);
    }
    pb = *(const float4*)(WT + (size_t)bk * N + bn + bc);
    As[0][ak+0][ar]=pa0.x; As[0][ak+1][ar]=pa0.y; As[0][ak+2][ar]=pa0.z; As[0][ak+3][ar]=pa0.w;
    As[0][ak+4][ar]=pa1.x; As[0][ak+5][ar]=pa1.y; As[0][ak+6][ar]=pa1.z; As[0][ak+7][ar]=pa1.w;
    *(float4*)&Bs[0][bk][bc] = pb;
    __syncthreads();

    int buf = 0;
    for (int k0 = 0; k0 < K1; k0 += 16, buf ^= 1) {
        const bool more = (k0 + 16) < K1;
        if (more) {
            int k = k0 + 16 + ak;
            pa0 = make_float4(0.f,0.f,0.f,0.f); pa1 = pa0;
            if (aok) {
                const float* p = A1 + (size_t)arow * lda1 + k;
                pa0 = *(const float4*)p;
                pa1 = *(const float4*)(p + 4);
            }
            pb = *(const float4*)(WT + (size_t)(k0 + 16 + bk) * N + bn + bc);
        }
        #pragma unroll
        for (int k = 0; k < 16; ++k) {
            float4 a0 = *(const float4*)&As[buf][k][ty * 8];
            float4 a1 = *(const float4*)&As[buf][k][ty * 8 + 4];
            float4 b  = *(const float4*)&Bs[buf][k][tx * 4];
            float av[8] = {a0.x, a0.y, a0.z, a0.w, a1.x, a1.y, a1.z, a1.w};
            #pragma unroll
            for (int r = 0; r < 8; ++r) {
                acc[r][0] += av[r] * b.x;
                acc[r][1] += av[r] * b.y;
                acc[r][2] += av[r] * b.z;
                acc[r][3] += av[r] * b.w;
            }
        }
        if (more) {
            int nb = buf ^ 1;
            As[nb][ak+0][ar]=pa0.x; As[nb][ak+1][ar]=pa0.y; As[nb][ak+2][ar]=pa0.z; As[nb][ak+3][ar]=pa0.w;
            As[nb][ak+4][ar]=pa1.x; As[nb][ak+5][ar]=pa1.y; As[nb][ak+6][ar]=pa1.z; As[nb][ak+7][ar]=pa1.w;
            *(float4*)&Bs[nb][bk][bc] = pb;
        }
        __syncthreads();
    }

    float4 bb = *(const float4*)(bias + bn + tx * 4);
    #pragma unroll
    for (int r = 0; r < 8; ++r) {
        int row = bm + ty * 8 + r;
        if (row >= M) continue;
        *(float4*)(G + (size_t)row * N + bn + tx * 4) =
            make_float4(acc[r][0]+bb.x, acc[r][1]+bb.y, acc[r][2]+bb.z, acc[r][3]+bb.w);
    }
}

// ---------------- persistent per-sequence LSTM ------------------------------
// Each block owns ~MAXI sequences and runs ALL STEPS internally.
// h in smem (ping-pong), c in registers; WhhT ([HD][4*HD], interleaved cols
// 4u+g) streamed from L2 each step with a 4-k register double-buffer.
// STEPS is a template param so per-i xw/rec addresses become single marched
// base pointers + compile-time immediate offsets (kills addressing IMADs).
// Thread layout: 256 threads = NRG row-groups x HD units (u = tid % HD).
// Group g handles local rows r = i*NRG + g; HROWS >= MAXI*NRG keeps every
// generated smem row index in bounds (dead rows stay zero).
// XW_PER_STEP=1: gate input row = m*STEPS + t (oe). =0: row = m, constant (od).
template<int HD, int NRG, int MAXI, int STEPS, int XW_PER_STEP>
__global__ void __launch_bounds__(256, 2)
persistent_lstm(const float* __restrict__ xw,
                const float* __restrict__ whhT,
                float* __restrict__ c_out,
                float* __restrict__ rec,
                int M) {
    constexpr int GN = 4 * HD;
    constexpr int HROWS = MAXI * NRG;
    constexpr long XW_ISTRIDE = (long)NRG * STEPS * GN;   // per-i xw offset (floats)
    constexpr long REC_ISTRIDE = (long)NRG * STEPS * HD;  // per-i rec offset (floats)
    __shared__ float hsm[2][HROWS][HD];
    const int tid = threadIdx.x;
    const int u = tid % HD;
    const int g = tid / HD;

    const int nb   = gridDim.x;
    const int base = M / nb;
    const int rem  = M - base * nb;
    const int bid  = blockIdx.x;
    const int nr    = base + (bid < rem ? 1 : 0);
    const int start = bid * base + (bid < rem ? bid : rem);

    float c[MAXI];
    float4 xwc[MAXI];
    #pragma unroll
    for (int i = 0; i < MAXI; i++) c[i] = 0.0f;

    if (!XW_PER_STEP) {
        #pragma unroll
        for (int i = 0; i < MAXI; i++) {
            int r = i * NRG + g;
            xwc[i] = (r < nr) ? *(const float4*)(xw + (size_t)(start + r) * GN + 4 * u)
                              : make_float4(0.f, 0.f, 0.f, 0.f);
        }
    }

    // zero BOTH h buffers
    for (int i = tid; i < 2 * HROWS * HD; i += 256) ((float*)hsm)[i] = 0.0f;
    __syncthreads();

    const float* wbase = whhT + 4 * u;                 // this thread's column
    // marched per-step bases (per-i handled by immediate offsets)
    const float* xw_t = xw + ((size_t)(start + g) * STEPS) * GN + 4 * u;
    float*       rec_t = rec ? rec + ((size_t)(start + g) * STEPS) * HD + u : nullptr;

    #pragma unroll 1
    for (int t = 0; t < STEPS; ++t) {
        const int cur = t & 1, nxt = cur ^ 1;
        float4 acc[MAXI];
        if (XW_PER_STEP) {
            #pragma unroll
            for (int i = 0; i < MAXI; i++) {
                int r = i * NRG + g;
                acc[i] = (r < nr) ? *(const float4*)(xw_t + i * XW_ISTRIDE)
                                  : make_float4(0.f, 0.f, 0.f, 0.f);
            }
        } else {
            #pragma unroll
            for (int i = 0; i < MAXI; i++) acc[i] = xwc[i];
        }
        if (t > 0) {
            // chunk 0 weights
            float4 wc0 = *(const float4*)(wbase + 0 * GN);
            float4 wc1 = *(const float4*)(wbase + 1 * GN);
            float4 wc2 = *(const float4*)(wbase + 2 * GN);
            float4 wc3 = *(const float4*)(wbase + 3 * GN);
            const float* wp = wbase + 4 * (size_t)GN;   // next chunk, marched
            #pragma unroll 1
            for (int k0 = 0; k0 < HD; k0 += 4) {
                float4 wn0, wn1, wn2, wn3;
                if (k0 + 4 < HD) {
                    wn0 = *(const float4*)(wp + 0 * GN);
                    wn1 = *(const float4*)(wp + 1 * GN);
                    wn2 = *(const float4*)(wp + 2 * GN);
                    wn3 = *(const float4*)(wp + 3 * GN);
                }
                #pragma unroll
                for (int i = 0; i < MAXI; i++) {
                    float4 h4 = *(const float4*)&hsm[cur][i * NRG + g][k0];  // LDS.128 bcast
                    acc[i].x += h4.x * wc0.x; acc[i].y += h4.x * wc0.y;
                    acc[i].z += h4.x * wc0.z; acc[i].w += h4.x * wc0.w;
                    acc[i].x += h4.y * wc1.x; acc[i].y += h4.y * wc1.y;
                    acc[i].z += h4.y * wc1.z; acc[i].w += h4.y * wc1.w;
                    acc[i].x += h4.z * wc2.x; acc[i].y += h4.z * wc2.y;
                    acc[i].z += h4.z * wc2.z; acc[i].w += h4.z * wc2.w;
                    acc[i].x += h4.w * wc3.x; acc[i].y += h4.w * wc3.y;
                    acc[i].z += h4.w * wc3.z; acc[i].w += h4.w * wc3.w;
                }
                if (k0 + 4 < HD) { wc0 = wn0; wc1 = wn1; wc2 = wn2; wc3 = wn3; }
                wp += 4 * (size_t)GN;
            }
        }
        // cell update + h write
        #pragma unroll
        for (int i = 0; i < MAXI; i++) {
            int r = i * NRG + g;
            float cc = sigf(acc[i].y) * c[i] + sigf(acc[i].x) * tanh_f(acc[i].z);
            c[i] = cc;
            float hh = sigf(acc[i].w) * tanh_f(cc);
            if (r < nr) {
                hsm[nxt][r][u] = hh;
                if (rec) rec_t[i * REC_ISTRIDE] = hh;
            }
        }
        __syncthreads();
        xw_t += GN;
        rec_t += HD;
    }

    if (c_out) {
        #pragma unroll
        for (int i = 0; i < MAXI; i++) {
            int r = i * NRG + g;
            if (r < nr) c_out[(size_t)(start + r) * HD + u] = c[i];
        }
    }
}

// ---------------- persistent inner LSTM (batch 32, 1 block per sequence) ----
// xw interleaved: row layout [u*4+g]; weights interleaved float4 per (k,u).
__global__ void __launch_bounds__(256)
inner_lstm(const float* __restrict__ xw, int xw_block_stride, int xw_step_stride,
           const float4* __restrict__ wp,
           float* __restrict__ out_c, float* __restrict__ out_h, int steps) {
    __shared__ float h[HDIM];
    int b = blockIdx.x;
    int u = threadIdx.x;
    float c = 0.0f;
    h[u] = 0.0f;
    __syncthreads();
    const float* xwb = xw + (size_t)b * xw_block_stride;
    for (int s = 0; s < steps; ++s) {
        float4 xg = *reinterpret_cast<const float4*>(xwb + (u << 2));
        float g0 = xg.x, g1 = xg.y, g2 = xg.z, g3 = xg.w;
        #pragma unroll 8
        for (int k = 0; k < HDIM; ++k) {
            float hk = h[k];
            float4 w = wp[(k << 8) + u];
            g0 += hk * w.x;
            g1 += hk * w.y;
            g2 += hk * w.z;
            g3 += hk * w.w;
        }
        float cc = sigf(g1) * c + sigf(g0) * tanh_f(g2);
        c = cc;
        float hh = sigf(g3) * tanh_f(cc);
        __syncthreads();
        h[u] = hh;
        __syncthreads();
        if (out_h) out_h[((size_t)b * steps + s) * HDIM + u] = hh;
        xwb += xw_step_stride;
    }
    if (out_c) out_c[b * HDIM + u] = c;
}

// ---------------- host orchestration ----------------------------------------
extern "C" void kernel_launch(void* const* d_in, const int* in_sizes, int n_in,
                              void* d_out, int out_size) {
    const float* inp    = (const float*)d_in[0];
    const float* oe_wih = (const float*)d_in[1];
    const float* oe_whh = (const float*)d_in[2];
    const float* oe_bih = (const float*)d_in[3];
    const float* oe_bhh = (const float*)d_in[4];
    const float* ie_wih = (const float*)d_in[5];
    const float* ie_whh = (const float*)d_in[6];
    const float* ie_bih = (const float*)d_in[7];
    const float* ie_bhh = (const float*)d_in[8];
    const float* id_wih = (const float*)d_in[9];
    const float* id_whh = (const float*)d_in[10];
    const float* id_bih = (const float*)d_in[11];
    const float* id_bhh = (const float*)d_in[12];
    const float* od_wih = (const float*)d_in[13];
    const float* od_whh = (const float*)d_in[14];
    const float* od_bih = (const float*)d_in[15];
    const float* od_bhh = (const float*)d_in[16];
    float* out = (float*)d_out;

    void* p;
    cudaGetSymbolAddress(&p, g_xT);      float* xT      = (float*)p;
    cudaGetSymbolAddress(&p, g_rec);     float* rec     = (float*)p;
    cudaGetSymbolAddress(&p, g_xw_oe);   float* xw_oe   = (float*)p;
    cudaGetSymbolAddress(&p, g_c);       float* c1      = (float*)p;
    cudaGetSymbolAddress(&p, g_xw_ie);   float* xw_ie   = (float*)p;
    cudaGetSymbolAddress(&p, g_bot);     float* bot     = (float*)p;
    cudaGetSymbolAddress(&p, g_xw_id);   float* xw_id   = (float*)p;
    cudaGetSymbolAddress(&p, g_dec);     float* decb    = (float*)p;
    cudaGetSymbolAddress(&p, g_xw_od);   float* xw_od   = (float*)p;
    cudaGetSymbolAddress(&p, g_oe_wT);   float* oe_wT   = (float*)p;
    cudaGetSymbolAddress(&p, g_oe_b);    float* oe_b    = (float*)p;
    cudaGetSymbolAddress(&p, g_ie_wihT); float* ie_wihT = (float*)p;
    cudaGetSymbolAddress(&p, g_ie_whhI); float* ie_whhI = (float*)p;
    cudaGetSymbolAddress(&p, g_ie_b);    float* ie_b    = (float*)p;
    cudaGetSymbolAddress(&p, g_id_wihT); float* id_wihT = (float*)p;
    cudaGetSymbolAddress(&p, g_id_whhI); float* id_whhI = (float*)p;
    cudaGetSymbolAddress(&p, g_id_b);    float* id_b    = (float*)p;
    cudaGetSymbolAddress(&p, g_od_wihT); float* od_wihT = (float*)p;
    cudaGetSymbolAddress(&p, g_od_whhT); float* od_whhT = (float*)p;
    cudaGetSymbolAddress(&p, g_od_b);    float* od_b    = (float*)p;

    dim3 tb(32, 8);

    // 0: all packing in one kernel
    pack_all<<<6406, 256>>>(oe_wih, oe_whh, ie_wih, ie_whh, id_wih, id_whh,
                            od_wih, od_whh,
                            oe_bih, oe_bhh, ie_bih, ie_bhh, id_bih, id_bhh,
                            od_bih, od_bhh,
                            oe_wT, ie_wihT, ie_whhI, id_wihT, id_whhI,
                            od_wihT, od_whhT, oe_b, ie_b, id_b, od_b);

    // 1: input transpose (B,F,T) -> (B,T,F)
    btrans<<<dim3(75, 4, B_), tb>>>(xT, inp, FBINS, TTOT);

    // 2: hoisted oe input gates for ALL timesteps (fully parallel)
    gemm_xw<<<dim3(16, 600), 256>>>(B_ * TTOT, 1024, xT, FBINS, FBINS,
                                    oe_wT, oe_b, xw_oe);

    // 3: outer encoder — persistent, 24 steps in-kernel, final c -> c1
    persistent_lstm<256, 1, 11, SEG_, 1><<<296, 256>>>(xw_oe, oe_wT + 128 * 1024,
                                                       c1, nullptr, BS_);

    // 4: inner encoder xw precompute
    gemm_xw<<<dim3(16, 25), 256>>>(BS_, 1024, c1, HDIM, HDIM, ie_wihT, ie_b, xw_ie);
    // 5: inner encoder (100 steps) -> bottleneck
    inner_lstm<<<B_, 256>>>(xw_ie, SSEG * 1024, 1024, (const float4*)ie_whhI,
                            bot, nullptr, SSEG);

    // 6: inner decoder xw (constant input per step)
    gemm_xw<<<dim3(16, 1), 256>>>(B_, 1024, bot, HDIM, HDIM, id_wihT, id_b, xw_id);
    // 7: inner decoder (100 steps) -> dec hidden states
    inner_lstm<<<B_, 256>>>(xw_id, 1024, 0, (const float4*)id_whhI,
                            nullptr, decb, SSEG);

    // 8: outer decoder xw (constant per segment)
    gemm_xw<<<dim3(8, 25), 256>>>(BS_, 512, decb, HDIM, HDIM, od_wihT, od_b, xw_od);
    // 9: outer decoder — persistent, 24 steps, h -> rec each step
    persistent_lstm<128, 2, 6, SEG_, 0><<<296, 256>>>(xw_od, od_whhT,
                                                      nullptr, rec, BS_);

    // 10: final transpose (B,T,F) -> (B,F,T)
    btrans<<<dim3(4, 75, B_), tb>>>(out, rec, TTOT, FBINS);
}